// round 3
// baseline (speedup 1.0000x reference)
#include <cuda_runtime.h>

#define NPTS 4096
#define BQ_K 32
#define M_PER_B (NPTS * BQ_K)   // 131072 columns per batch
#define NBATCH 2

// ---------------- scratch (device globals; no allocations) ----------------
__device__ float g_x0[NBATCH * 13  * M_PER_B];   // fused features, [b][c][m]
__device__ float g_x1[NBATCH * 64  * M_PER_B];   // conv0 out (raw, pre-GN)
__device__ float g_x2[NBATCH * 64  * M_PER_B];   // conv1 out (raw, pre-GN)
__device__ float g_mx[NBATCH * 128 * NPTS];      // max over k of conv2 out (raw)
__device__ float g_mn[NBATCH * 128 * NPTS];      // min over k of conv2 out (raw)
__device__ float g_part[3][NBATCH * 512 * 8 * 2]; // per-block GN partial sums
__device__ float g_mr[3][NBATCH * 8 * 2];        // per-(b,group) mean/rstd

// ---------------- helpers ----------------
__device__ __forceinline__ float lo32(unsigned long long v) {
    return __uint_as_float((unsigned)(v & 0xffffffffull));
}
__device__ __forceinline__ float hi32(unsigned long long v) {
    return __uint_as_float((unsigned)(v >> 32));
}
// packed fp32x2 FMA (sm_103a): a = w*y + a, elementwise on two packed floats
__device__ __forceinline__ void ffma2(unsigned long long& a,
                                      unsigned long long w,
                                      unsigned long long y) {
    asm("fma.rn.f32x2 %0, %1, %2, %0;" : "+l"(a) : "l"(w), "l"(y));
}

__device__ __forceinline__ float angle3(float ax, float ay, float az,
                                        float bx, float by, float bz) {
    float cx = ay * bz - az * by;
    float cy = az * bx - ax * bz;
    float cz = ax * by - ay * bx;
    float s = cx * cx + cy * cy + cz * cz;
    float y = s > 0.f ? sqrtf(s) : 0.f;
    float x = ax * bx + ay * by + az * bz;
    if (y == 0.f && x == 0.f) return 0.f;
    return atan2f(y, x);
}

// ---------------- kernel 1: ball query + fused 13-ch features ----------------
__global__ void __launch_bounds__(256) ball_feat_kernel(
    const float* __restrict__ xyz, const float* __restrict__ feat,
    const float* __restrict__ wa, const float* __restrict__ wb,
    const float* __restrict__ wc)
{
    __shared__ float sx[NPTS * 3];  // 48KB
    const int b = blockIdx.y;
    const float* xb = xyz + (size_t)b * NPTS * 3;
    const float* fb = feat + (size_t)b * NPTS * 3;
    for (int i = threadIdx.x; i < NPTS * 3; i += 256) sx[i] = xb[i];
    __syncthreads();

    const int warp = threadIdx.x >> 5;
    const int lane = threadIdx.x & 31;
    const int i = blockIdx.x * 8 + warp;

    const float cx = sx[i * 3 + 0], cy = sx[i * 3 + 1], cz = sx[i * 3 + 2];
    const float R2 = (float)(0.1 * 0.1);

    int myj = 0;
    int found = 0;
    for (int jb = 0; jb < NPTS; jb += 32) {
        int j = jb + lane;
        float dx = sx[j * 3 + 0] - cx;
        float dy = sx[j * 3 + 1] - cy;
        float dz = sx[j * 3 + 2] - cz;
        float d2 = __fadd_rn(__fadd_rn(__fmul_rn(dx, dx), __fmul_rn(dy, dy)),
                             __fmul_rn(dz, dz));
        unsigned m = __ballot_sync(0xffffffffu, d2 <= R2);
        int cnt = __popc(m);
        if (lane >= found && lane < found + cnt) {
            int pos = __fns(m, 0, lane - found + 1);
            myj = jb + pos;
        }
        found += cnt;
        if (found >= BQ_K) break;
    }
    int j0 = __shfl_sync(0xffffffffu, myj, 0);
    if (lane >= found) myj = j0;

    float gx = sx[myj * 3 + 0], gy = sx[myj * 3 + 1], gz = sx[myj * 3 + 2];
    float nx = __ldg(fb + myj * 3 + 0), ny = __ldg(fb + myj * 3 + 1), nz = __ldg(fb + myj * 3 + 2);
    float rx = __ldg(fb + i * 3 + 0),  ry = __ldg(fb + i * 3 + 1),  rz = __ldg(fb + i * 3 + 2);
    float dx = gx - cx, dy = gy - cy, dz = gz - cz;
    float sq = dx * dx + dy * dy + dz * dz;
    float dist = sq > 0.f ? sqrtf(sq) : 0.f;
    float a1 = angle3(rx, ry, rz, dx, dy, dz);
    float a2 = angle3(nx, ny, nz, dx, dy, dz);
    float a3 = angle3(rx, ry, rz, nx, ny, nz);
    float A = __ldg(wa), Bv = __ldg(wb), Cv = __ldg(wc);

    float* o = g_x0 + (size_t)b * 13 * M_PER_B + (size_t)i * 32 + lane;
    o[0 * M_PER_B]  = A * cx;  o[1 * M_PER_B]  = A * cy;  o[2 * M_PER_B]  = A * cz;
    o[3 * M_PER_B]  = A * gx;  o[4 * M_PER_B]  = A * gy;  o[5 * M_PER_B]  = A * gz;
    o[6 * M_PER_B]  = Bv * dx; o[7 * M_PER_B]  = Bv * dy; o[8 * M_PER_B]  = Bv * dz;
    o[9 * M_PER_B]  = Bv * dist;
    o[10 * M_PER_B] = Cv * a1; o[11 * M_PER_B] = Cv * a2; o[12 * M_PER_B] = Cv * a3;
}

// ---------------- fused GEMM + (input GN/ReLU) + stats (+ max/min epilogue) ----
// Thread tile: 8 outputs x 8 columns. Warp = 8 outputs (one GN group for O=64).
// Weights in smem transposed [C][O] as duplicated {w,w} so each channel's 8
// output weights are one contiguous 64B run of broadcast LDS.128 loads.
template <int LAYER>
__global__ void __launch_bounds__(LAYER == 2 ? 512 : 256, LAYER == 2 ? 1 : 2)
gemm_gn_kernel(const float* __restrict__ W, const float* __restrict__ gamma,
               const float* __restrict__ beta)
{
    constexpr int C     = (LAYER == 0) ? 13 : 64;
    constexpr int O     = (LAYER == 2) ? 128 : 64;
    constexpr int NT    = (LAYER == 2) ? 512 : 256;
    constexpr bool GN_IN = (LAYER > 0);
    constexpr bool LAST  = (LAYER == 2);

    extern __shared__ unsigned char smraw[];
    float2* Wp     = (float2*)smraw;                                 // [C][O] {w,w}
    float*  Xs     = (float*)(smraw + sizeof(float2) * O * C);       // [C][256]
    float*  sScale = Xs + C * 256;                                   // [64]
    float*  sShift = sScale + 64;                                    // [64]
    float*  sWsum  = sShift + 64;                                    // [NW*2]

    const int tid = threadIdx.x;
    const int b   = blockIdx.y;
    const int m0  = blockIdx.x * 256;

    for (int idx = tid; idx < O * C; idx += NT) {
        int o = idx / C, c = idx - o * C;
        float w = W[idx];
        Wp[c * O + o] = make_float2(w, w);
    }
    if (GN_IN && tid < C) {
        const float* mr = g_mr[LAYER - 1] + b * 16;
        int gg = tid >> 3;                 // C=64 here, 8 channels per group
        float s = mr[gg * 2 + 1] * gamma[tid];
        sScale[tid] = s;
        sShift[tid] = beta[tid] - mr[gg * 2] * s;
    }
    __syncthreads();

    // ---- stage X tile (vectorized, fused input-GN+ReLU) ----
    const float* xin = (LAYER == 0) ? g_x0 : ((LAYER == 1) ? g_x1 : g_x2);
    const float* xbp = xin + (size_t)b * C * M_PER_B + m0;
    for (int idx = tid; idx < C * 64; idx += NT) {
        int ci = idx >> 6;
        int c4 = (idx & 63) << 2;
        float4 v = *(const float4*)&xbp[(size_t)ci * M_PER_B + c4];
        if (GN_IN) {
            float s = sScale[ci], t = sShift[ci];
            v.x = fmaxf(s * v.x + t, 0.f);
            v.y = fmaxf(s * v.y + t, 0.f);
            v.z = fmaxf(s * v.z + t, 0.f);
            v.w = fmaxf(s * v.w + t, 0.f);
        }
        *(float4*)&Xs[ci * 256 + c4] = v;
    }
    __syncthreads();

    const int ob   = tid >> 5;      // warp id: owns outputs [8ob, 8ob+8)
    const int cg   = tid & 31;      // owns columns [cg*8, cg*8+8)
    const float* xcol = Xs + cg * 8;
    const unsigned long long* wb64 = (const unsigned long long*)Wp + ob * 8;

    unsigned long long acc[8][4];
#pragma unroll
    for (int a = 0; a < 8; a++) {
        acc[a][0] = 0ull; acc[a][1] = 0ull; acc[a][2] = 0ull; acc[a][3] = 0ull;
    }

    // software-pipelined channel loop: prefetch y(i+1) while doing FMAs of y(i)
    ulonglong2 yc0 = *(const ulonglong2*)&xcol[0];
    ulonglong2 yc1 = *(const ulonglong2*)&xcol[4];
#pragma unroll 4
    for (int i = 0; i < C; i++) {
        const int inx = (i + 1 < C) ? (i + 1) : i;
        ulonglong2 yn0 = *(const ulonglong2*)&xcol[inx * 256];
        ulonglong2 yn1 = *(const ulonglong2*)&xcol[inx * 256 + 4];
        const ulonglong2* wrow = (const ulonglong2*)(wb64 + (size_t)i * O);
#pragma unroll
        for (int q = 0; q < 4; q++) {
            ulonglong2 w2 = wrow[q];             // broadcast LDS.128: outs 2q, 2q+1
            ffma2(acc[2 * q][0], w2.x, yc0.x);
            ffma2(acc[2 * q][1], w2.x, yc0.y);
            ffma2(acc[2 * q][2], w2.x, yc1.x);
            ffma2(acc[2 * q][3], w2.x, yc1.y);
            ffma2(acc[2 * q + 1][0], w2.y, yc0.x);
            ffma2(acc[2 * q + 1][1], w2.y, yc0.y);
            ffma2(acc[2 * q + 1][2], w2.y, yc1.x);
            ffma2(acc[2 * q + 1][3], w2.y, yc1.y);
        }
        yc0 = yn0;
        yc1 = yn1;
    }

    // ---- epilogue ----
    if (!LAST) {
        float* xo = ((LAYER == 0) ? g_x1 : g_x2)
                    + (size_t)b * O * M_PER_B + m0 + cg * 8;
#pragma unroll
        for (int oo = 0; oo < 8; oo++) {
            float4 v0, v1;
            v0.x = lo32(acc[oo][0]); v0.y = hi32(acc[oo][0]);
            v0.z = lo32(acc[oo][1]); v0.w = hi32(acc[oo][1]);
            v1.x = lo32(acc[oo][2]); v1.y = hi32(acc[oo][2]);
            v1.z = lo32(acc[oo][3]); v1.w = hi32(acc[oo][3]);
            *(float4*)&xo[(size_t)(ob * 8 + oo) * M_PER_B]     = v0;
            *(float4*)&xo[(size_t)(ob * 8 + oo) * M_PER_B + 4] = v1;
        }
    } else {
        // columns m = m0 + cg*8 .. +7 all belong to n = blockIdx.x*8 + cg/4;
        // lanes with equal cg>>2 (4 lanes) cover the 32 k's of that n.
        int n = blockIdx.x * 8 + (cg >> 2);
#pragma unroll
        for (int oo = 0; oo < 8; oo++) {
            float v0 = lo32(acc[oo][0]), v1 = hi32(acc[oo][0]);
            float v2 = lo32(acc[oo][1]), v3 = hi32(acc[oo][1]);
            float v4 = lo32(acc[oo][2]), v5 = hi32(acc[oo][2]);
            float v6 = lo32(acc[oo][3]), v7 = hi32(acc[oo][3]);
            float mx = fmaxf(fmaxf(fmaxf(v0, v1), fmaxf(v2, v3)),
                             fmaxf(fmaxf(v4, v5), fmaxf(v6, v7)));
            float mn = fminf(fminf(fminf(v0, v1), fminf(v2, v3)),
                             fminf(fminf(v4, v5), fminf(v6, v7)));
            mx = fmaxf(mx, __shfl_xor_sync(0xffffffffu, mx, 1));
            mn = fminf(mn, __shfl_xor_sync(0xffffffffu, mn, 1));
            mx = fmaxf(mx, __shfl_xor_sync(0xffffffffu, mx, 2));
            mn = fminf(mn, __shfl_xor_sync(0xffffffffu, mn, 2));
            if ((cg & 3) == 0) {
                int o = ob * 8 + oo;
                g_mx[((size_t)b * O + o) * NPTS + n] = mx;
                g_mn[((size_t)b * O + o) * NPTS + n] = mn;
            }
        }
    }

    // ---- GN stats partials (warp covers one group for O=64, half for O=128) ----
    {
        float S = 0.f, Q = 0.f;
#pragma unroll
        for (int oo = 0; oo < 8; oo++) {
#pragma unroll
            for (int p = 0; p < 4; p++) {
                float v0 = lo32(acc[oo][p]), v1 = hi32(acc[oo][p]);
                S += v0 + v1;
                Q += v0 * v0 + v1 * v1;
            }
        }
#pragma unroll
        for (int d = 16; d > 0; d >>= 1) {
            S += __shfl_xor_sync(0xffffffffu, S, d);
            Q += __shfl_xor_sync(0xffffffffu, Q, d);
        }
        if ((tid & 31) == 0) {
            sWsum[ob * 2 + 0] = S;
            sWsum[ob * 2 + 1] = Q;
        }
    }
    __syncthreads();
    if (tid < 8) {
        float S, Q;
        if (O == 64) {                       // group g == warp g
            S = sWsum[tid * 2 + 0];
            Q = sWsum[tid * 2 + 1];
        } else {                             // group g = warps {2g, 2g+1}
            S = sWsum[(2 * tid) * 2 + 0] + sWsum[(2 * tid + 1) * 2 + 0];
            Q = sWsum[(2 * tid) * 2 + 1] + sWsum[(2 * tid + 1) * 2 + 1];
        }
        float* pp = g_part[LAYER] + (((size_t)b * gridDim.x + blockIdx.x) * 8 + tid) * 2;
        pp[0] = S;
        pp[1] = Q;
    }
}

// ---------------- per-(b,group) stats reduce ----------------
template <int LAYER>
__global__ void __launch_bounds__(256) reduce_stats_kernel()
{
    constexpr float INV = (LAYER == 2) ? (1.f / 2097152.f) : (1.f / 1048576.f);
    const int b = blockIdx.x >> 3, g = blockIdx.x & 7;
    __shared__ float sS[256], sQ[256];
    float S = 0.f, Q = 0.f;
    for (int mb = threadIdx.x; mb < 512; mb += 256) {
        const float* p = g_part[LAYER] + (((size_t)b * 512 + mb) * 8 + g) * 2;
        S += p[0];
        Q += p[1];
    }
    sS[threadIdx.x] = S; sQ[threadIdx.x] = Q;
    __syncthreads();
    for (int d = 128; d > 0; d >>= 1) {
        if (threadIdx.x < d) {
            sS[threadIdx.x] += sS[threadIdx.x + d];
            sQ[threadIdx.x] += sQ[threadIdx.x + d];
        }
        __syncthreads();
    }
    if (threadIdx.x == 0) {
        float mean = sS[0] * INV;
        float var  = sQ[0] * INV - mean * mean;
        g_mr[LAYER][b * 16 + g * 2 + 0] = mean;
        g_mr[LAYER][b * 16 + g * 2 + 1] = rsqrtf(var + 1e-5f);
    }
}

// ---------------- finalize ----------------
__global__ void __launch_bounds__(256) finalize_kernel(
    const float* __restrict__ gamma, const float* __restrict__ beta,
    float* __restrict__ out)
{
    int i = blockIdx.x * 256 + threadIdx.x;       // [b][o][n], 2*128*4096
    int o = (i >> 12) & 127;
    int b = i >> 19;
    int g = o >> 4;
    const float* mr = g_mr[2] + b * 16 + g * 2;
    float s = mr[1] * gamma[o];
    float t = beta[o] - mr[0] * s;
    float v = (s >= 0.f) ? (s * g_mx[i] + t) : (s * g_mn[i] + t);
    out[i] = fmaxf(v, 0.f);
    out[2 * 128 * NPTS + i] = v;
}

// ---------------- launch ----------------
extern "C" void kernel_launch(void* const* d_in, const int* in_sizes, int n_in,
                              void* d_out, int out_size)
{
    const float* feature = (const float*)d_in[0];
    const float* xyz     = (const float*)d_in[1];
    const float* w0  = (const float*)d_in[2];
    const float* gg0 = (const float*)d_in[3];
    const float* gb0 = (const float*)d_in[4];
    const float* w1  = (const float*)d_in[5];
    const float* gg1 = (const float*)d_in[6];
    const float* gb1 = (const float*)d_in[7];
    const float* w2  = (const float*)d_in[8];
    const float* gg2 = (const float*)d_in[9];
    const float* gb2 = (const float*)d_in[10];
    const float* wa  = (const float*)d_in[11];
    const float* wb  = (const float*)d_in[12];
    const float* wc  = (const float*)d_in[13];
    float* out = (float*)d_out;

    // dynamic smem: Wp(O*C*8) + Xs(C*256*4) + scale/shift(512) + sWsum(NW*8)
    const int sm0 = 64 * 13 * 8  + 13 * 256 * 4 + 512 + 8 * 8;
    const int sm1 = 64 * 64 * 8  + 64 * 256 * 4 + 512 + 8 * 8;
    const int sm2 = 128 * 64 * 8 + 64 * 256 * 4 + 512 + 16 * 8;
    cudaFuncSetAttribute(gemm_gn_kernel<0>, cudaFuncAttributeMaxDynamicSharedMemorySize, sm0);
    cudaFuncSetAttribute(gemm_gn_kernel<1>, cudaFuncAttributeMaxDynamicSharedMemorySize, sm1);
    cudaFuncSetAttribute(gemm_gn_kernel<2>, cudaFuncAttributeMaxDynamicSharedMemorySize, sm2);

    ball_feat_kernel<<<dim3(512, 2), 256>>>(xyz, feature, wa, wb, wc);

    gemm_gn_kernel<0><<<dim3(512, 2), 256, sm0>>>(w0, gg0, gb0);
    reduce_stats_kernel<0><<<16, 256>>>();

    gemm_gn_kernel<1><<<dim3(512, 2), 256, sm1>>>(w1, gg0, gb0);
    reduce_stats_kernel<1><<<16, 256>>>();

    gemm_gn_kernel<2><<<dim3(512, 2), 512, sm2>>>(w2, gg1, gb1);
    reduce_stats_kernel<2><<<16, 256>>>();

    finalize_kernel<<<4096, 256>>>(gg2, gb2, out);
}

// round 4
// speedup vs baseline: 1.0075x; 1.0075x over previous
#include <cuda_runtime.h>

#define NPTS 4096
#define BQ_K 32
#define M_PER_B (NPTS * BQ_K)   // 131072 columns per batch
#define NBATCH 2

// ---------------- scratch (device globals; no allocations) ----------------
__device__ float g_x0[NBATCH * 13  * M_PER_B];   // fused features, [b][c][m]
__device__ float g_x1[NBATCH * 64  * M_PER_B];   // conv0 out (raw, pre-GN)
__device__ float g_x2[NBATCH * 64  * M_PER_B];   // conv1 out (raw, pre-GN)
__device__ float g_mx[NBATCH * 128 * NPTS];      // max over k of conv2 out (raw)
__device__ float g_mn[NBATCH * 128 * NPTS];      // min over k of conv2 out (raw)
__device__ float g_part[3][NBATCH * 512 * 8 * 2]; // per-block GN partial sums
__device__ float g_mr[3][NBATCH * 8 * 2];        // per-(b,group) mean/rstd

// ---------------- helpers ----------------
__device__ __forceinline__ float lo32(unsigned long long v) {
    return __uint_as_float((unsigned)(v & 0xffffffffull));
}
__device__ __forceinline__ float hi32(unsigned long long v) {
    return __uint_as_float((unsigned)(v >> 32));
}
// packed fp32x2 FMA (sm_103a): a = w*y + a, elementwise on two packed floats
__device__ __forceinline__ void ffma2(unsigned long long& a,
                                      unsigned long long w,
                                      unsigned long long y) {
    asm("fma.rn.f32x2 %0, %1, %2, %0;" : "+l"(a) : "l"(w), "l"(y));
}

__device__ __forceinline__ float angle3(float ax, float ay, float az,
                                        float bx, float by, float bz) {
    float cx = ay * bz - az * by;
    float cy = az * bx - ax * bz;
    float cz = ax * by - ay * bx;
    float s = cx * cx + cy * cy + cz * cz;
    float y = s > 0.f ? sqrtf(s) : 0.f;
    float x = ax * bx + ay * by + az * bz;
    if (y == 0.f && x == 0.f) return 0.f;
    return atan2f(y, x);
}

// ---------------- kernel 1: ball query + fused 13-ch features ----------------
__global__ void __launch_bounds__(256) ball_feat_kernel(
    const float* __restrict__ xyz, const float* __restrict__ feat,
    const float* __restrict__ wa, const float* __restrict__ wb,
    const float* __restrict__ wc)
{
    __shared__ float sx[NPTS * 3];  // 48KB
    const int b = blockIdx.y;
    const float* xb = xyz + (size_t)b * NPTS * 3;
    const float* fb = feat + (size_t)b * NPTS * 3;
    for (int i = threadIdx.x; i < NPTS * 3; i += 256) sx[i] = xb[i];
    __syncthreads();

    const int warp = threadIdx.x >> 5;
    const int lane = threadIdx.x & 31;
    const int i = blockIdx.x * 8 + warp;

    const float cx = sx[i * 3 + 0], cy = sx[i * 3 + 1], cz = sx[i * 3 + 2];
    const float R2 = (float)(0.1 * 0.1);

    int myj = 0;
    int found = 0;
    for (int jb = 0; jb < NPTS; jb += 32) {
        int j = jb + lane;
        float dx = sx[j * 3 + 0] - cx;
        float dy = sx[j * 3 + 1] - cy;
        float dz = sx[j * 3 + 2] - cz;
        float d2 = __fadd_rn(__fadd_rn(__fmul_rn(dx, dx), __fmul_rn(dy, dy)),
                             __fmul_rn(dz, dz));
        unsigned m = __ballot_sync(0xffffffffu, d2 <= R2);
        int cnt = __popc(m);
        if (lane >= found && lane < found + cnt) {
            int pos = __fns(m, 0, lane - found + 1);
            myj = jb + pos;
        }
        found += cnt;
        if (found >= BQ_K) break;
    }
    int j0 = __shfl_sync(0xffffffffu, myj, 0);
    if (lane >= found) myj = j0;

    float gx = sx[myj * 3 + 0], gy = sx[myj * 3 + 1], gz = sx[myj * 3 + 2];
    float nx = __ldg(fb + myj * 3 + 0), ny = __ldg(fb + myj * 3 + 1), nz = __ldg(fb + myj * 3 + 2);
    float rx = __ldg(fb + i * 3 + 0),  ry = __ldg(fb + i * 3 + 1),  rz = __ldg(fb + i * 3 + 2);
    float dx = gx - cx, dy = gy - cy, dz = gz - cz;
    float sq = dx * dx + dy * dy + dz * dz;
    float dist = sq > 0.f ? sqrtf(sq) : 0.f;
    float a1 = angle3(rx, ry, rz, dx, dy, dz);
    float a2 = angle3(nx, ny, nz, dx, dy, dz);
    float a3 = angle3(rx, ry, rz, nx, ny, nz);
    float A = __ldg(wa), Bv = __ldg(wb), Cv = __ldg(wc);

    float* o = g_x0 + (size_t)b * 13 * M_PER_B + (size_t)i * 32 + lane;
    o[0 * M_PER_B]  = A * cx;  o[1 * M_PER_B]  = A * cy;  o[2 * M_PER_B]  = A * cz;
    o[3 * M_PER_B]  = A * gx;  o[4 * M_PER_B]  = A * gy;  o[5 * M_PER_B]  = A * gz;
    o[6 * M_PER_B]  = Bv * dx; o[7 * M_PER_B]  = Bv * dy; o[8 * M_PER_B]  = Bv * dz;
    o[9 * M_PER_B]  = Bv * dist;
    o[10 * M_PER_B] = Cv * a1; o[11 * M_PER_B] = Cv * a2; o[12 * M_PER_B] = Cv * a3;
}

// 32 FFMA2 block: 8 outputs (pairs in w0..w3, each {lo,hi}=2 outs) x 8 cols
#define FMA_CH(W0, W1, W2, W3, Y0, Y1)            \
    do {                                          \
        ffma2(acc[0][0], (W0).x, (Y0).x);         \
        ffma2(acc[0][1], (W0).x, (Y0).y);         \
        ffma2(acc[0][2], (W0).x, (Y1).x);         \
        ffma2(acc[0][3], (W0).x, (Y1).y);         \
        ffma2(acc[1][0], (W0).y, (Y0).x);         \
        ffma2(acc[1][1], (W0).y, (Y0).y);         \
        ffma2(acc[1][2], (W0).y, (Y1).x);         \
        ffma2(acc[1][3], (W0).y, (Y1).y);         \
        ffma2(acc[2][0], (W1).x, (Y0).x);         \
        ffma2(acc[2][1], (W1).x, (Y0).y);         \
        ffma2(acc[2][2], (W1).x, (Y1).x);         \
        ffma2(acc[2][3], (W1).x, (Y1).y);         \
        ffma2(acc[3][0], (W1).y, (Y0).x);         \
        ffma2(acc[3][1], (W1).y, (Y0).y);         \
        ffma2(acc[3][2], (W1).y, (Y1).x);         \
        ffma2(acc[3][3], (W1).y, (Y1).y);         \
        ffma2(acc[4][0], (W2).x, (Y0).x);         \
        ffma2(acc[4][1], (W2).x, (Y0).y);         \
        ffma2(acc[4][2], (W2).x, (Y1).x);         \
        ffma2(acc[4][3], (W2).x, (Y1).y);         \
        ffma2(acc[5][0], (W2).y, (Y0).x);         \
        ffma2(acc[5][1], (W2).y, (Y0).y);         \
        ffma2(acc[5][2], (W2).y, (Y1).x);         \
        ffma2(acc[5][3], (W2).y, (Y1).y);         \
        ffma2(acc[6][0], (W3).x, (Y0).x);         \
        ffma2(acc[6][1], (W3).x, (Y0).y);         \
        ffma2(acc[6][2], (W3).x, (Y1).x);         \
        ffma2(acc[6][3], (W3).x, (Y1).y);         \
        ffma2(acc[7][0], (W3).y, (Y0).x);         \
        ffma2(acc[7][1], (W3).y, (Y0).y);         \
        ffma2(acc[7][2], (W3).y, (Y1).x);         \
        ffma2(acc[7][3], (W3).y, (Y1).y);         \
    } while (0)

// ---------------- fused GEMM + (input GN/ReLU) + stats (+ max/min epilogue) ----
// Thread tile: 8 outputs x 8 columns. Warp = 8 outputs (one GN group for O=64).
// Weights in smem transposed [C][O] as duplicated {w,w}: channel's 8 output
// weights = 4 contiguous broadcast LDS.128.
template <int LAYER>
__global__ void __launch_bounds__(LAYER == 2 ? 512 : 256, LAYER == 2 ? 1 : 2)
gemm_gn_kernel(const float* __restrict__ W, const float* __restrict__ gamma,
               const float* __restrict__ beta)
{
    constexpr int C     = (LAYER == 0) ? 13 : 64;
    constexpr int O     = (LAYER == 2) ? 128 : 64;
    constexpr int NT    = (LAYER == 2) ? 512 : 256;
    constexpr bool GN_IN = (LAYER > 0);
    constexpr bool LAST  = (LAYER == 2);

    extern __shared__ unsigned char smraw[];
    float2* Wp     = (float2*)smraw;                                 // [C][O] {w,w}
    float*  Xs     = (float*)(smraw + sizeof(float2) * O * C);       // [C][256]
    float*  sScale = Xs + C * 256;                                   // [64]
    float*  sShift = sScale + 64;                                    // [64]
    float*  sWsum  = sShift + 64;                                    // [NW*2]

    const int tid = threadIdx.x;
    const int b   = blockIdx.y;
    const int m0  = blockIdx.x * 256;

    for (int idx = tid; idx < O * C; idx += NT) {
        int o = idx / C, c = idx - o * C;
        float w = W[idx];
        Wp[c * O + o] = make_float2(w, w);
    }
    if (GN_IN && tid < C) {
        const float* mr = g_mr[LAYER - 1] + b * 16;
        int gg = tid >> 3;                 // C=64 here, 8 channels per group
        float s = mr[gg * 2 + 1] * gamma[tid];
        sScale[tid] = s;
        sShift[tid] = beta[tid] - mr[gg * 2] * s;
    }
    __syncthreads();

    // ---- stage X tile (vectorized, fused input-GN+ReLU) ----
    const float* xin = (LAYER == 0) ? g_x0 : ((LAYER == 1) ? g_x1 : g_x2);
    const float* xbp = xin + (size_t)b * C * M_PER_B + m0;
    for (int idx = tid; idx < C * 64; idx += NT) {
        int ci = idx >> 6;
        int c4 = (idx & 63) << 2;
        float4 v = *(const float4*)&xbp[(size_t)ci * M_PER_B + c4];
        if (GN_IN) {
            float s = sScale[ci], t = sShift[ci];
            v.x = fmaxf(s * v.x + t, 0.f);
            v.y = fmaxf(s * v.y + t, 0.f);
            v.z = fmaxf(s * v.z + t, 0.f);
            v.w = fmaxf(s * v.w + t, 0.f);
        }
        *(float4*)&Xs[ci * 256 + c4] = v;
    }
    __syncthreads();

    const int ob   = tid >> 5;      // warp id: owns outputs [8ob, 8ob+8)
    const int cg   = tid & 31;      // owns columns [cg*8, cg*8+8)
    const float* xcol = Xs + cg * 8;
    const unsigned long long* wb64 = (const unsigned long long*)Wp + ob * 8;

    unsigned long long acc[8][4];
#pragma unroll
    for (int a = 0; a < 8; a++) {
        acc[a][0] = 0ull; acc[a][1] = 0ull; acc[a][2] = 0ull; acc[a][3] = 0ull;
    }

    if (C & 1) {   // layer 0, C=13: simple path (6% of FLOPs)
#pragma unroll
        for (int i = 0; i < C; i++) {
            ulonglong2 y0 = *(const ulonglong2*)&xcol[i * 256];
            ulonglong2 y1 = *(const ulonglong2*)&xcol[i * 256 + 4];
            const ulonglong2* wr = (const ulonglong2*)(wb64 + (size_t)i * O);
            ulonglong2 w0 = wr[0], w1 = wr[1], w2 = wr[2], w3 = wr[3];
            FMA_CH(w0, w1, w2, w3, y0, y1);
        }
    } else {
        // distance-2 software pipeline over channels: slot A = even, B = odd.
        ulonglong2 wA0, wA1, wA2, wA3, yA0, yA1;
        ulonglong2 wB0, wB1, wB2, wB3, yB0, yB1;
        {
            const ulonglong2* wrA = (const ulonglong2*)(wb64);
            const ulonglong2* wrB = (const ulonglong2*)(wb64 + O);
            wA0 = wrA[0]; wA1 = wrA[1]; wA2 = wrA[2]; wA3 = wrA[3];
            wB0 = wrB[0]; wB1 = wrB[1]; wB2 = wrB[2]; wB3 = wrB[3];
            yA0 = *(const ulonglong2*)&xcol[0];
            yA1 = *(const ulonglong2*)&xcol[4];
            yB0 = *(const ulonglong2*)&xcol[256];
            yB1 = *(const ulonglong2*)&xcol[260];
        }
#pragma unroll 1
        for (int i = 0; i < C; i += 2) {
            // clamp prefetch index so last iteration re-reads (harmless)
            int ia = (i + 2 < C) ? (i + 2) : (C - 2);
            int ib = ia + 1;

            FMA_CH(wA0, wA1, wA2, wA3, yA0, yA1);   // channel i

            {   // prefetch channel ia into slot A (used 64 FMA-issues later)
                const ulonglong2* wr = (const ulonglong2*)(wb64 + (size_t)ia * O);
                wA0 = wr[0]; wA1 = wr[1]; wA2 = wr[2]; wA3 = wr[3];
                yA0 = *(const ulonglong2*)&xcol[ia * 256];
                yA1 = *(const ulonglong2*)&xcol[ia * 256 + 4];
            }

            FMA_CH(wB0, wB1, wB2, wB3, yB0, yB1);   // channel i+1

            {   // prefetch channel ib into slot B
                const ulonglong2* wr = (const ulonglong2*)(wb64 + (size_t)ib * O);
                wB0 = wr[0]; wB1 = wr[1]; wB2 = wr[2]; wB3 = wr[3];
                yB0 = *(const ulonglong2*)&xcol[ib * 256];
                yB1 = *(const ulonglong2*)&xcol[ib * 256 + 4];
            }
        }
    }

    // ---- epilogue ----
    if (!LAST) {
        float* xo = ((LAYER == 0) ? g_x1 : g_x2)
                    + (size_t)b * O * M_PER_B + m0 + cg * 8;
#pragma unroll
        for (int oo = 0; oo < 8; oo++) {
            float4 v0, v1;
            v0.x = lo32(acc[oo][0]); v0.y = hi32(acc[oo][0]);
            v0.z = lo32(acc[oo][1]); v0.w = hi32(acc[oo][1]);
            v1.x = lo32(acc[oo][2]); v1.y = hi32(acc[oo][2]);
            v1.z = lo32(acc[oo][3]); v1.w = hi32(acc[oo][3]);
            *(float4*)&xo[(size_t)(ob * 8 + oo) * M_PER_B]     = v0;
            *(float4*)&xo[(size_t)(ob * 8 + oo) * M_PER_B + 4] = v1;
        }
    } else {
        // columns m = m0 + cg*8 .. +7 all belong to n = blockIdx.x*8 + cg/4;
        // lanes with equal cg>>2 (4 lanes) cover the 32 k's of that n.
        int n = blockIdx.x * 8 + (cg >> 2);
#pragma unroll
        for (int oo = 0; oo < 8; oo++) {
            float v0 = lo32(acc[oo][0]), v1 = hi32(acc[oo][0]);
            float v2 = lo32(acc[oo][1]), v3 = hi32(acc[oo][1]);
            float v4 = lo32(acc[oo][2]), v5 = hi32(acc[oo][2]);
            float v6 = lo32(acc[oo][3]), v7 = hi32(acc[oo][3]);
            float mx = fmaxf(fmaxf(fmaxf(v0, v1), fmaxf(v2, v3)),
                             fmaxf(fmaxf(v4, v5), fmaxf(v6, v7)));
            float mn = fminf(fminf(fminf(v0, v1), fminf(v2, v3)),
                             fminf(fminf(v4, v5), fminf(v6, v7)));
            mx = fmaxf(mx, __shfl_xor_sync(0xffffffffu, mx, 1));
            mn = fminf(mn, __shfl_xor_sync(0xffffffffu, mn, 1));
            mx = fmaxf(mx, __shfl_xor_sync(0xffffffffu, mx, 2));
            mn = fminf(mn, __shfl_xor_sync(0xffffffffu, mn, 2));
            if ((cg & 3) == 0) {
                int o = ob * 8 + oo;
                g_mx[((size_t)b * O + o) * NPTS + n] = mx;
                g_mn[((size_t)b * O + o) * NPTS + n] = mn;
            }
        }
    }

    // ---- GN stats partials (warp covers one group for O=64, half for O=128) ----
    {
        float S = 0.f, Q = 0.f;
#pragma unroll
        for (int oo = 0; oo < 8; oo++) {
#pragma unroll
            for (int p = 0; p < 4; p++) {
                float v0 = lo32(acc[oo][p]), v1 = hi32(acc[oo][p]);
                S += v0 + v1;
                Q += v0 * v0 + v1 * v1;
            }
        }
#pragma unroll
        for (int d = 16; d > 0; d >>= 1) {
            S += __shfl_xor_sync(0xffffffffu, S, d);
            Q += __shfl_xor_sync(0xffffffffu, Q, d);
        }
        if ((tid & 31) == 0) {
            sWsum[ob * 2 + 0] = S;
            sWsum[ob * 2 + 1] = Q;
        }
    }
    __syncthreads();
    if (tid < 8) {
        float S, Q;
        if (O == 64) {                       // group g == warp g
            S = sWsum[tid * 2 + 0];
            Q = sWsum[tid * 2 + 1];
        } else {                             // group g = warps {2g, 2g+1}
            S = sWsum[(2 * tid) * 2 + 0] + sWsum[(2 * tid + 1) * 2 + 0];
            Q = sWsum[(2 * tid) * 2 + 1] + sWsum[(2 * tid + 1) * 2 + 1];
        }
        float* pp = g_part[LAYER] + (((size_t)b * gridDim.x + blockIdx.x) * 8 + tid) * 2;
        pp[0] = S;
        pp[1] = Q;
    }
}

// ---------------- per-(b,group) stats reduce ----------------
template <int LAYER>
__global__ void __launch_bounds__(256) reduce_stats_kernel()
{
    constexpr float INV = (LAYER == 2) ? (1.f / 2097152.f) : (1.f / 1048576.f);
    const int b = blockIdx.x >> 3, g = blockIdx.x & 7;
    __shared__ float sS[256], sQ[256];
    float S = 0.f, Q = 0.f;
    for (int mb = threadIdx.x; mb < 512; mb += 256) {
        const float* p = g_part[LAYER] + (((size_t)b * 512 + mb) * 8 + g) * 2;
        S += p[0];
        Q += p[1];
    }
    sS[threadIdx.x] = S; sQ[threadIdx.x] = Q;
    __syncthreads();
    for (int d = 128; d > 0; d >>= 1) {
        if (threadIdx.x < d) {
            sS[threadIdx.x] += sS[threadIdx.x + d];
            sQ[threadIdx.x] += sQ[threadIdx.x + d];
        }
        __syncthreads();
    }
    if (threadIdx.x == 0) {
        float mean = sS[0] * INV;
        float var  = sQ[0] * INV - mean * mean;
        g_mr[LAYER][b * 16 + g * 2 + 0] = mean;
        g_mr[LAYER][b * 16 + g * 2 + 1] = rsqrtf(var + 1e-5f);
    }
}

// ---------------- finalize ----------------
__global__ void __launch_bounds__(256) finalize_kernel(
    const float* __restrict__ gamma, const float* __restrict__ beta,
    float* __restrict__ out)
{
    int i = blockIdx.x * 256 + threadIdx.x;       // [b][o][n], 2*128*4096
    int o = (i >> 12) & 127;
    int b = i >> 19;
    int g = o >> 4;
    const float* mr = g_mr[2] + b * 16 + g * 2;
    float s = mr[1] * gamma[o];
    float t = beta[o] - mr[0] * s;
    float v = (s >= 0.f) ? (s * g_mx[i] + t) : (s * g_mn[i] + t);
    out[i] = fmaxf(v, 0.f);
    out[2 * 128 * NPTS + i] = v;
}

// ---------------- launch ----------------
extern "C" void kernel_launch(void* const* d_in, const int* in_sizes, int n_in,
                              void* d_out, int out_size)
{
    const float* feature = (const float*)d_in[0];
    const float* xyz     = (const float*)d_in[1];
    const float* w0  = (const float*)d_in[2];
    const float* gg0 = (const float*)d_in[3];
    const float* gb0 = (const float*)d_in[4];
    const float* w1  = (const float*)d_in[5];
    const float* gg1 = (const float*)d_in[6];
    const float* gb1 = (const float*)d_in[7];
    const float* w2  = (const float*)d_in[8];
    const float* gg2 = (const float*)d_in[9];
    const float* gb2 = (const float*)d_in[10];
    const float* wa  = (const float*)d_in[11];
    const float* wb  = (const float*)d_in[12];
    const float* wc  = (const float*)d_in[13];
    float* out = (float*)d_out;

    // dynamic smem: Wp(O*C*8) + Xs(C*256*4) + scale/shift(512) + sWsum(NW*8)
    const int sm0 = 64 * 13 * 8  + 13 * 256 * 4 + 512 + 8 * 8;
    const int sm1 = 64 * 64 * 8  + 64 * 256 * 4 + 512 + 8 * 8;
    const int sm2 = 128 * 64 * 8 + 64 * 256 * 4 + 512 + 16 * 8;
    cudaFuncSetAttribute(gemm_gn_kernel<0>, cudaFuncAttributeMaxDynamicSharedMemorySize, sm0);
    cudaFuncSetAttribute(gemm_gn_kernel<1>, cudaFuncAttributeMaxDynamicSharedMemorySize, sm1);
    cudaFuncSetAttribute(gemm_gn_kernel<2>, cudaFuncAttributeMaxDynamicSharedMemorySize, sm2);

    ball_feat_kernel<<<dim3(512, 2), 256>>>(xyz, feature, wa, wb, wc);

    gemm_gn_kernel<0><<<dim3(512, 2), 256, sm0>>>(w0, gg0, gb0);
    reduce_stats_kernel<0><<<16, 256>>>();

    gemm_gn_kernel<1><<<dim3(512, 2), 256, sm1>>>(w1, gg0, gb0);
    reduce_stats_kernel<1><<<16, 256>>>();

    gemm_gn_kernel<2><<<dim3(512, 2), 512, sm2>>>(w2, gg1, gb1);
    reduce_stats_kernel<2><<<16, 256>>>();

    finalize_kernel<<<4096, 256>>>(gg2, gb2, out);
}

// round 5
// speedup vs baseline: 1.0456x; 1.0378x over previous
#include <cuda_runtime.h>

#define NPTS 4096
#define BQ_K 32
#define M_PER_B (NPTS * BQ_K)   // 131072 columns per batch
#define NBATCH 2

// ---------------- scratch (device globals; no allocations) ----------------
__device__ float g_x0[NBATCH * 13  * M_PER_B];   // fused features, [b][c][m]
__device__ float g_x1[NBATCH * 64  * M_PER_B];   // conv0 out (raw, pre-GN)
__device__ float g_x2[NBATCH * 64  * M_PER_B];   // conv1 out (raw, pre-GN)
__device__ float g_mx[NBATCH * 128 * NPTS];      // max over k of conv2 out (raw)
__device__ float g_mn[NBATCH * 128 * NPTS];      // min over k of conv2 out (raw)
__device__ float g_part[3][NBATCH * 512 * 8 * 2]; // per-block GN partial sums
__device__ float g_mr[3][NBATCH * 8 * 2];        // per-(b,group) mean/rstd

// ---------------- helpers ----------------
__device__ __forceinline__ float lo32(unsigned long long v) {
    return __uint_as_float((unsigned)(v & 0xffffffffull));
}
__device__ __forceinline__ float hi32(unsigned long long v) {
    return __uint_as_float((unsigned)(v >> 32));
}
// packed fp32x2 FMA (sm_103a): a = w*y + a, elementwise on two packed floats
__device__ __forceinline__ void ffma2(unsigned long long& a,
                                      unsigned long long w,
                                      unsigned long long y) {
    asm("fma.rn.f32x2 %0, %1, %2, %0;" : "+l"(a) : "l"(w), "l"(y));
}

__device__ __forceinline__ float angle3(float ax, float ay, float az,
                                        float bx, float by, float bz) {
    float cx = ay * bz - az * by;
    float cy = az * bx - ax * bz;
    float cz = ax * by - ay * bx;
    float s = cx * cx + cy * cy + cz * cz;
    float y = s > 0.f ? sqrtf(s) : 0.f;
    float x = ax * bx + ay * by + az * bz;
    if (y == 0.f && x == 0.f) return 0.f;
    return atan2f(y, x);
}

// ---------------- kernel 1: ball query + fused 13-ch features ----------------
__global__ void __launch_bounds__(256) ball_feat_kernel(
    const float* __restrict__ xyz, const float* __restrict__ feat,
    const float* __restrict__ wa, const float* __restrict__ wb,
    const float* __restrict__ wc)
{
    __shared__ float sx[NPTS * 3];  // 48KB
    const int b = blockIdx.y;
    const float* xb = xyz + (size_t)b * NPTS * 3;
    const float* fb = feat + (size_t)b * NPTS * 3;
    for (int i = threadIdx.x; i < NPTS * 3; i += 256) sx[i] = xb[i];
    __syncthreads();

    const int warp = threadIdx.x >> 5;
    const int lane = threadIdx.x & 31;
    const int i = blockIdx.x * 8 + warp;

    const float cx = sx[i * 3 + 0], cy = sx[i * 3 + 1], cz = sx[i * 3 + 2];
    const float R2 = (float)(0.1 * 0.1);

    int myj = 0;
    int found = 0;
    for (int jb = 0; jb < NPTS; jb += 32) {
        int j = jb + lane;
        float dx = sx[j * 3 + 0] - cx;
        float dy = sx[j * 3 + 1] - cy;
        float dz = sx[j * 3 + 2] - cz;
        float d2 = __fadd_rn(__fadd_rn(__fmul_rn(dx, dx), __fmul_rn(dy, dy)),
                             __fmul_rn(dz, dz));
        unsigned m = __ballot_sync(0xffffffffu, d2 <= R2);
        int cnt = __popc(m);
        if (lane >= found && lane < found + cnt) {
            int pos = __fns(m, 0, lane - found + 1);
            myj = jb + pos;
        }
        found += cnt;
        if (found >= BQ_K) break;
    }
    int j0 = __shfl_sync(0xffffffffu, myj, 0);
    if (lane >= found) myj = j0;

    float gx = sx[myj * 3 + 0], gy = sx[myj * 3 + 1], gz = sx[myj * 3 + 2];
    float nx = __ldg(fb + myj * 3 + 0), ny = __ldg(fb + myj * 3 + 1), nz = __ldg(fb + myj * 3 + 2);
    float rx = __ldg(fb + i * 3 + 0),  ry = __ldg(fb + i * 3 + 1),  rz = __ldg(fb + i * 3 + 2);
    float dx = gx - cx, dy = gy - cy, dz = gz - cz;
    float sq = dx * dx + dy * dy + dz * dz;
    float dist = sq > 0.f ? sqrtf(sq) : 0.f;
    float a1 = angle3(rx, ry, rz, dx, dy, dz);
    float a2 = angle3(nx, ny, nz, dx, dy, dz);
    float a3 = angle3(rx, ry, rz, nx, ny, nz);
    float A = __ldg(wa), Bv = __ldg(wb), Cv = __ldg(wc);

    float* o = g_x0 + (size_t)b * 13 * M_PER_B + (size_t)i * 32 + lane;
    o[0 * M_PER_B]  = A * cx;  o[1 * M_PER_B]  = A * cy;  o[2 * M_PER_B]  = A * cz;
    o[3 * M_PER_B]  = A * gx;  o[4 * M_PER_B]  = A * gy;  o[5 * M_PER_B]  = A * gz;
    o[6 * M_PER_B]  = Bv * dx; o[7 * M_PER_B]  = Bv * dy; o[8 * M_PER_B]  = Bv * dz;
    o[9 * M_PER_B]  = Bv * dist;
    o[10 * M_PER_B] = Cv * a1; o[11 * M_PER_B] = Cv * a2; o[12 * M_PER_B] = Cv * a3;
}

// 32 FFMA2 block: 8 outputs (pairs in w0..w3, each {lo,hi}=2 outs) x 8 cols
#define FMA_CH(W0, W1, W2, W3, Y0, Y1)            \
    do {                                          \
        ffma2(acc[0][0], (W0).x, (Y0).x);         \
        ffma2(acc[0][1], (W0).x, (Y0).y);         \
        ffma2(acc[0][2], (W0).x, (Y1).x);         \
        ffma2(acc[0][3], (W0).x, (Y1).y);         \
        ffma2(acc[1][0], (W0).y, (Y0).x);         \
        ffma2(acc[1][1], (W0).y, (Y0).y);         \
        ffma2(acc[1][2], (W0).y, (Y1).x);         \
        ffma2(acc[1][3], (W0).y, (Y1).y);         \
        ffma2(acc[2][0], (W1).x, (Y0).x);         \
        ffma2(acc[2][1], (W1).x, (Y0).y);         \
        ffma2(acc[2][2], (W1).x, (Y1).x);         \
        ffma2(acc[2][3], (W1).x, (Y1).y);         \
        ffma2(acc[3][0], (W1).y, (Y0).x);         \
        ffma2(acc[3][1], (W1).y, (Y0).y);         \
        ffma2(acc[3][2], (W1).y, (Y1).x);         \
        ffma2(acc[3][3], (W1).y, (Y1).y);         \
        ffma2(acc[4][0], (W2).x, (Y0).x);         \
        ffma2(acc[4][1], (W2).x, (Y0).y);         \
        ffma2(acc[4][2], (W2).x, (Y1).x);         \
        ffma2(acc[4][3], (W2).x, (Y1).y);         \
        ffma2(acc[5][0], (W2).y, (Y0).x);         \
        ffma2(acc[5][1], (W2).y, (Y0).y);         \
        ffma2(acc[5][2], (W2).y, (Y1).x);         \
        ffma2(acc[5][3], (W2).y, (Y1).y);         \
        ffma2(acc[6][0], (W3).x, (Y0).x);         \
        ffma2(acc[6][1], (W3).x, (Y0).y);         \
        ffma2(acc[6][2], (W3).x, (Y1).x);         \
        ffma2(acc[6][3], (W3).x, (Y1).y);         \
        ffma2(acc[7][0], (W3).y, (Y0).x);         \
        ffma2(acc[7][1], (W3).y, (Y0).y);         \
        ffma2(acc[7][2], (W3).y, (Y1).x);         \
        ffma2(acc[7][3], (W3).y, (Y1).y);         \
    } while (0)

// ---------------- fused GEMM + (input GN/ReLU) + stats (+ max/min epilogue) ----
// Thread tile: 8 outputs x 8 columns. The 8 columns are TWO disjoint float4
// chunks: [cg*4, cg*4+4) and [cg*4+128, cg*4+132)  -> lane stride 16B
// -> conflict-free LDS.128 (4 wavefronts instead of 8).
// Weights in smem transposed [C][O] as duplicated {w,w}: channel's 8 output
// weights = 4 contiguous broadcast LDS.128.
template <int LAYER>
__global__ void __launch_bounds__(LAYER == 2 ? 512 : 256, LAYER == 2 ? 1 : 2)
gemm_gn_kernel(const float* __restrict__ W, const float* __restrict__ gamma,
               const float* __restrict__ beta)
{
    constexpr int C     = (LAYER == 0) ? 13 : 64;
    constexpr int O     = (LAYER == 2) ? 128 : 64;
    constexpr int NT    = (LAYER == 2) ? 512 : 256;
    constexpr bool GN_IN = (LAYER > 0);
    constexpr bool LAST  = (LAYER == 2);

    extern __shared__ unsigned char smraw[];
    float2* Wp     = (float2*)smraw;                                 // [C][O] {w,w}
    float*  Xs     = (float*)(smraw + sizeof(float2) * O * C);       // [C][256]
    float*  sScale = Xs + C * 256;                                   // [64]
    float*  sShift = sScale + 64;                                    // [64]
    float*  sWsum  = sShift + 64;                                    // [NW*2]

    const int tid = threadIdx.x;
    const int b   = blockIdx.y;
    const int m0  = blockIdx.x * 256;

    for (int idx = tid; idx < O * C; idx += NT) {
        int o = idx / C, c = idx - o * C;
        float w = W[idx];
        Wp[c * O + o] = make_float2(w, w);
    }
    if (GN_IN && tid < C) {
        const float* mr = g_mr[LAYER - 1] + b * 16;
        int gg = tid >> 3;                 // C=64 here, 8 channels per group
        float s = mr[gg * 2 + 1] * gamma[tid];
        sScale[tid] = s;
        sShift[tid] = beta[tid] - mr[gg * 2] * s;
    }
    __syncthreads();

    // ---- stage X tile (vectorized, fused input-GN+ReLU) ----
    const float* xin = (LAYER == 0) ? g_x0 : ((LAYER == 1) ? g_x1 : g_x2);
    const float* xbp = xin + (size_t)b * C * M_PER_B + m0;
    for (int idx = tid; idx < C * 64; idx += NT) {
        int ci = idx >> 6;
        int c4 = (idx & 63) << 2;
        float4 v = *(const float4*)&xbp[(size_t)ci * M_PER_B + c4];
        if (GN_IN) {
            float s = sScale[ci], t = sShift[ci];
            v.x = fmaxf(s * v.x + t, 0.f);
            v.y = fmaxf(s * v.y + t, 0.f);
            v.z = fmaxf(s * v.z + t, 0.f);
            v.w = fmaxf(s * v.w + t, 0.f);
        }
        *(float4*)&Xs[ci * 256 + c4] = v;
    }
    __syncthreads();

    const int ob   = tid >> 5;      // warp id: owns outputs [8ob, 8ob+8)
    const int cg   = tid & 31;      // columns cg*4.. and 128+cg*4..
    const float* xcol = Xs + cg * 4;
    const unsigned long long* wb64 = (const unsigned long long*)Wp + ob * 8;

    unsigned long long acc[8][4];
#pragma unroll
    for (int a = 0; a < 8; a++) {
        acc[a][0] = 0ull; acc[a][1] = 0ull; acc[a][2] = 0ull; acc[a][3] = 0ull;
    }

#pragma unroll 4
    for (int i = 0; i < C; i++) {
        ulonglong2 y0 = *(const ulonglong2*)&xcol[i * 256];        // cols cg*4..+3
        ulonglong2 y1 = *(const ulonglong2*)&xcol[i * 256 + 128];  // cols 128+cg*4..+3
        const ulonglong2* wr = (const ulonglong2*)(wb64 + (size_t)i * O);
        ulonglong2 w0 = wr[0], w1 = wr[1], w2 = wr[2], w3 = wr[3];
        FMA_CH(w0, w1, w2, w3, y0, y1);
    }

    // ---- epilogue ----
    if (!LAST) {
        float* xo = ((LAYER == 0) ? g_x1 : g_x2)
                    + (size_t)b * O * M_PER_B + m0 + cg * 4;
#pragma unroll
        for (int oo = 0; oo < 8; oo++) {
            float4 v0, v1;
            v0.x = lo32(acc[oo][0]); v0.y = hi32(acc[oo][0]);
            v0.z = lo32(acc[oo][1]); v0.w = hi32(acc[oo][1]);
            v1.x = lo32(acc[oo][2]); v1.y = hi32(acc[oo][2]);
            v1.z = lo32(acc[oo][3]); v1.w = hi32(acc[oo][3]);
            *(float4*)&xo[(size_t)(ob * 8 + oo) * M_PER_B]       = v0;
            *(float4*)&xo[(size_t)(ob * 8 + oo) * M_PER_B + 128] = v1;
        }
    } else {
        // chunk 1: cols m0+cg*4   -> n1 = blockIdx*8 + (cg>>3),   k = (cg&7)*4..
        // chunk 2: cols m0+128+.. -> n2 = n1 + 4
        // lanes with same cg>>3 (8 lanes, consecutive) cover all 32 k's.
        int n1 = blockIdx.x * 8 + (cg >> 3);
#pragma unroll
        for (int oo = 0; oo < 8; oo++) {
            float v0 = lo32(acc[oo][0]), v1 = hi32(acc[oo][0]);
            float v2 = lo32(acc[oo][1]), v3 = hi32(acc[oo][1]);
            float v4 = lo32(acc[oo][2]), v5 = hi32(acc[oo][2]);
            float v6 = lo32(acc[oo][3]), v7 = hi32(acc[oo][3]);
            float mxa = fmaxf(fmaxf(v0, v1), fmaxf(v2, v3));
            float mna = fminf(fminf(v0, v1), fminf(v2, v3));
            float mxb = fmaxf(fmaxf(v4, v5), fmaxf(v6, v7));
            float mnb = fminf(fminf(v4, v5), fminf(v6, v7));
#pragma unroll
            for (int d = 1; d < 8; d <<= 1) {
                mxa = fmaxf(mxa, __shfl_xor_sync(0xffffffffu, mxa, d));
                mna = fminf(mna, __shfl_xor_sync(0xffffffffu, mna, d));
                mxb = fmaxf(mxb, __shfl_xor_sync(0xffffffffu, mxb, d));
                mnb = fminf(mnb, __shfl_xor_sync(0xffffffffu, mnb, d));
            }
            if ((cg & 7) == 0) {
                int o = ob * 8 + oo;
                size_t base = ((size_t)b * O + o) * NPTS;
                g_mx[base + n1]     = mxa;
                g_mn[base + n1]     = mna;
                g_mx[base + n1 + 4] = mxb;
                g_mn[base + n1 + 4] = mnb;
            }
        }
    }

    // ---- GN stats partials (warp covers one group for O=64, half for O=128) ----
    {
        float S = 0.f, Q = 0.f;
#pragma unroll
        for (int oo = 0; oo < 8; oo++) {
#pragma unroll
            for (int p = 0; p < 4; p++) {
                float v0 = lo32(acc[oo][p]), v1 = hi32(acc[oo][p]);
                S += v0 + v1;
                Q += v0 * v0 + v1 * v1;
            }
        }
#pragma unroll
        for (int d = 16; d > 0; d >>= 1) {
            S += __shfl_xor_sync(0xffffffffu, S, d);
            Q += __shfl_xor_sync(0xffffffffu, Q, d);
        }
        if ((tid & 31) == 0) {
            sWsum[ob * 2 + 0] = S;
            sWsum[ob * 2 + 1] = Q;
        }
    }
    __syncthreads();
    if (tid < 8) {
        float S, Q;
        if (O == 64) {                       // group g == warp g
            S = sWsum[tid * 2 + 0];
            Q = sWsum[tid * 2 + 1];
        } else {                             // group g = warps {2g, 2g+1}
            S = sWsum[(2 * tid) * 2 + 0] + sWsum[(2 * tid + 1) * 2 + 0];
            Q = sWsum[(2 * tid) * 2 + 1] + sWsum[(2 * tid + 1) * 2 + 1];
        }
        float* pp = g_part[LAYER] + (((size_t)b * gridDim.x + blockIdx.x) * 8 + tid) * 2;
        pp[0] = S;
        pp[1] = Q;
    }
}

// ---------------- per-(b,group) stats reduce ----------------
template <int LAYER>
__global__ void __launch_bounds__(256) reduce_stats_kernel()
{
    constexpr float INV = (LAYER == 2) ? (1.f / 2097152.f) : (1.f / 1048576.f);
    const int b = blockIdx.x >> 3, g = blockIdx.x & 7;
    __shared__ float sS[256], sQ[256];
    float S = 0.f, Q = 0.f;
    for (int mb = threadIdx.x; mb < 512; mb += 256) {
        const float* p = g_part[LAYER] + (((size_t)b * 512 + mb) * 8 + g) * 2;
        S += p[0];
        Q += p[1];
    }
    sS[threadIdx.x] = S; sQ[threadIdx.x] = Q;
    __syncthreads();
    for (int d = 128; d > 0; d >>= 1) {
        if (threadIdx.x < d) {
            sS[threadIdx.x] += sS[threadIdx.x + d];
            sQ[threadIdx.x] += sQ[threadIdx.x + d];
        }
        __syncthreads();
    }
    if (threadIdx.x == 0) {
        float mean = sS[0] * INV;
        float var  = sQ[0] * INV - mean * mean;
        g_mr[LAYER][b * 16 + g * 2 + 0] = mean;
        g_mr[LAYER][b * 16 + g * 2 + 1] = rsqrtf(var + 1e-5f);
    }
}

// ---------------- finalize ----------------
__global__ void __launch_bounds__(256) finalize_kernel(
    const float* __restrict__ gamma, const float* __restrict__ beta,
    float* __restrict__ out)
{
    int i = blockIdx.x * 256 + threadIdx.x;       // [b][o][n], 2*128*4096
    int o = (i >> 12) & 127;
    int b = i >> 19;
    int g = o >> 4;
    const float* mr = g_mr[2] + b * 16 + g * 2;
    float s = mr[1] * gamma[o];
    float t = beta[o] - mr[0] * s;
    float v = (s >= 0.f) ? (s * g_mx[i] + t) : (s * g_mn[i] + t);
    out[i] = fmaxf(v, 0.f);
    out[2 * 128 * NPTS + i] = v;
}

// ---------------- launch ----------------
extern "C" void kernel_launch(void* const* d_in, const int* in_sizes, int n_in,
                              void* d_out, int out_size)
{
    const float* feature = (const float*)d_in[0];
    const float* xyz     = (const float*)d_in[1];
    const float* w0  = (const float*)d_in[2];
    const float* gg0 = (const float*)d_in[3];
    const float* gb0 = (const float*)d_in[4];
    const float* w1  = (const float*)d_in[5];
    const float* gg1 = (const float*)d_in[6];
    const float* gb1 = (const float*)d_in[7];
    const float* w2  = (const float*)d_in[8];
    const float* gg2 = (const float*)d_in[9];
    const float* gb2 = (const float*)d_in[10];
    const float* wa  = (const float*)d_in[11];
    const float* wb  = (const float*)d_in[12];
    const float* wc  = (const float*)d_in[13];
    float* out = (float*)d_out;

    // dynamic smem: Wp(O*C*8) + Xs(C*256*4) + scale/shift(512) + sWsum(NW*8)
    const int sm0 = 64 * 13 * 8  + 13 * 256 * 4 + 512 + 8 * 8;
    const int sm1 = 64 * 64 * 8  + 64 * 256 * 4 + 512 + 8 * 8;
    const int sm2 = 128 * 64 * 8 + 64 * 256 * 4 + 512 + 16 * 8;
    cudaFuncSetAttribute(gemm_gn_kernel<0>, cudaFuncAttributeMaxDynamicSharedMemorySize, sm0);
    cudaFuncSetAttribute(gemm_gn_kernel<1>, cudaFuncAttributeMaxDynamicSharedMemorySize, sm1);
    cudaFuncSetAttribute(gemm_gn_kernel<2>, cudaFuncAttributeMaxDynamicSharedMemorySize, sm2);

    ball_feat_kernel<<<dim3(512, 2), 256>>>(xyz, feature, wa, wb, wc);

    gemm_gn_kernel<0><<<dim3(512, 2), 256, sm0>>>(w0, gg0, gb0);
    reduce_stats_kernel<0><<<16, 256>>>();

    gemm_gn_kernel<1><<<dim3(512, 2), 256, sm1>>>(w1, gg0, gb0);
    reduce_stats_kernel<1><<<16, 256>>>();

    gemm_gn_kernel<2><<<dim3(512, 2), 512, sm2>>>(w2, gg1, gb1);
    reduce_stats_kernel<2><<<16, 256>>>();

    finalize_kernel<<<4096, 256>>>(gg2, gb2, out);
}

// round 7
// speedup vs baseline: 1.1361x; 1.0865x over previous
#include <cuda_runtime.h>
#include <cstdint>
#include <cfloat>

#define NPTS 4096
#define BQ_K 32
#define M_PER_B (NPTS * BQ_K)   // max 131072 columns per batch
#define NBATCH 2

// ---------------- scratch (device globals; no allocations) ----------------
__device__ float g_x0[NBATCH * 13  * M_PER_B];   // compacted fused features
__device__ float g_x1[NBATCH * 64  * M_PER_B];   // conv0 out (compacted)
__device__ float g_x2[NBATCH * 64  * M_PER_B];   // conv1 out (compacted)
__device__ float g_y2[NBATCH * 128 * M_PER_B];   // conv2 out (compacted)
__device__ float g_wt[NBATCH * M_PER_B];         // per-column stats weight
__device__ int   g_idx[NBATCH * NPTS * BQ_K];    // neighbor lists
__device__ int   g_cnt[NBATCH * NPTS];           // per-point unique count
__device__ int   g_off[NBATCH * NPTS];           // exclusive offsets
__device__ int   g_meta[NBATCH * 2];             // {total, padded_total}
__device__ float g_mx[NBATCH * 128 * NPTS];      // max over k (raw conv2)
__device__ float g_mn[NBATCH * 128 * NPTS];      // min over k (raw conv2)
__device__ float g_part[3][NBATCH * 512 * 8 * 2]; // per-block GN partials
__device__ float g_mr[3][NBATCH * 8 * 2];        // per-(b,group) mean/rstd

// ---------------- helpers ----------------
__device__ __forceinline__ float lo32(unsigned long long v) {
    return __uint_as_float((unsigned)(v & 0xffffffffull));
}
__device__ __forceinline__ float hi32(unsigned long long v) {
    return __uint_as_float((unsigned)(v >> 32));
}
__device__ __forceinline__ void ffma2(unsigned long long& a,
                                      unsigned long long w,
                                      unsigned long long y) {
    asm("fma.rn.f32x2 %0, %1, %2, %0;" : "+l"(a) : "l"(w), "l"(y));
}

__device__ __forceinline__ float angle3(float ax, float ay, float az,
                                        float bx, float by, float bz) {
    float cx = ay * bz - az * by;
    float cy = az * bx - ax * bz;
    float cz = ax * by - ay * bx;
    float s = cx * cx + cy * cy + cz * cz;
    float y = s > 0.f ? sqrtf(s) : 0.f;
    float x = ax * bx + ay * by + az * bz;
    if (y == 0.f && x == 0.f) return 0.f;
    return atan2f(y, x);
}

// ---------------- K1: ball query (counts + neighbor lists) ----------------
__global__ void __launch_bounds__(256) ball_count_kernel(
    const float* __restrict__ xyz)
{
    __shared__ float sx[NPTS * 3];  // 48KB
    const int b = blockIdx.y;
    const float* xb = xyz + (size_t)b * NPTS * 3;
    for (int i = threadIdx.x; i < NPTS * 3; i += 256) sx[i] = xb[i];
    __syncthreads();

    const int warp = threadIdx.x >> 5;
    const int lane = threadIdx.x & 31;
    const int i = blockIdx.x * 8 + warp;

    const float cx = sx[i * 3 + 0], cy = sx[i * 3 + 1], cz = sx[i * 3 + 2];
    const float R2 = (float)(0.1 * 0.1);

    int myj = 0;
    int found = 0;
    for (int jb = 0; jb < NPTS; jb += 32) {
        int j = jb + lane;
        float dx = sx[j * 3 + 0] - cx;
        float dy = sx[j * 3 + 1] - cy;
        float dz = sx[j * 3 + 2] - cz;
        float d2 = __fadd_rn(__fadd_rn(__fmul_rn(dx, dx), __fmul_rn(dy, dy)),
                             __fmul_rn(dz, dz));
        unsigned m = __ballot_sync(0xffffffffu, d2 <= R2);
        int cnt = __popc(m);
        if (lane >= found && lane < found + cnt) {
            int pos = __fns(m, 0, lane - found + 1);
            myj = jb + pos;   // lane == k slot (ascending j order)
        }
        found += cnt;
        if (found >= BQ_K) break;
    }
    int c = found < BQ_K ? found : BQ_K;
    if (lane < c) g_idx[((size_t)b * NPTS + i) * BQ_K + lane] = myj;
    if (lane == 0) g_cnt[b * NPTS + i] = c;
}

// ---------------- K2: deterministic block scan of counts ----------------
__global__ void __launch_bounds__(1024) scan_kernel()
{
    __shared__ int sp[1024];
    const int t = threadIdx.x;
    const int b = blockIdx.x;
    int4 cv = ((const int4*)(g_cnt + b * NPTS))[t];
    int s0 = cv.x;
    int s1 = s0 + cv.y;
    int s2 = s1 + cv.z;
    int s3 = s2 + cv.w;
    sp[t] = s3;
    __syncthreads();
    for (int d = 1; d < 1024; d <<= 1) {
        int u = (t >= d) ? sp[t - d] : 0;
        __syncthreads();
        sp[t] += u;
        __syncthreads();
    }
    int e = (t > 0) ? sp[t - 1] : 0;
    int base = b * NPTS + t * 4;
    g_off[base + 0] = e;
    g_off[base + 1] = e + s0;
    g_off[base + 2] = e + s1;
    g_off[base + 3] = e + s2;
    if (t == 1023) {
        int tot = sp[1023];
        g_meta[b * 2 + 0] = tot;
        g_meta[b * 2 + 1] = (tot + 255) & ~255;
    }
}

// ---------------- K3: compacted 13-ch features + weights ----------------
__global__ void __launch_bounds__(256) feat_kernel(
    const float* __restrict__ xyz, const float* __restrict__ feat,
    const float* __restrict__ wa, const float* __restrict__ wb,
    const float* __restrict__ wc)
{
    const int b = blockIdx.y;
    const int warp = threadIdx.x >> 5;
    const int lane = threadIdx.x & 31;
    const int i = blockIdx.x * 8 + warp;

    const int c   = g_cnt[b * NPTS + i];
    const int off = g_off[b * NPTS + i];
    if (lane >= c) return;

    const float* xb = xyz + (size_t)b * NPTS * 3;
    const float* fb = feat + (size_t)b * NPTS * 3;
    int j = g_idx[((size_t)b * NPTS + i) * BQ_K + lane];

    float cx = __ldg(xb + i * 3 + 0), cy = __ldg(xb + i * 3 + 1), cz = __ldg(xb + i * 3 + 2);
    float gx = __ldg(xb + j * 3 + 0), gy = __ldg(xb + j * 3 + 1), gz = __ldg(xb + j * 3 + 2);
    float nx = __ldg(fb + j * 3 + 0), ny = __ldg(fb + j * 3 + 1), nz = __ldg(fb + j * 3 + 2);
    float rx = __ldg(fb + i * 3 + 0), ry = __ldg(fb + i * 3 + 1), rz = __ldg(fb + i * 3 + 2);
    float dx = gx - cx, dy = gy - cy, dz = gz - cz;
    float sq = dx * dx + dy * dy + dz * dz;
    float dist = sq > 0.f ? sqrtf(sq) : 0.f;
    float a1 = angle3(rx, ry, rz, dx, dy, dz);
    float a2 = angle3(nx, ny, nz, dx, dy, dz);
    float a3 = angle3(rx, ry, rz, nx, ny, nz);
    float A = __ldg(wa), Bv = __ldg(wb), Cv = __ldg(wc);

    int col = off + lane;
    float* o = g_x0 + (size_t)b * 13 * M_PER_B + col;
    o[0 * M_PER_B]  = A * cx;  o[1 * M_PER_B]  = A * cy;  o[2 * M_PER_B]  = A * cz;
    o[3 * M_PER_B]  = A * gx;  o[4 * M_PER_B]  = A * gy;  o[5 * M_PER_B]  = A * gz;
    o[6 * M_PER_B]  = Bv * dx; o[7 * M_PER_B]  = Bv * dy; o[8 * M_PER_B]  = Bv * dz;
    o[9 * M_PER_B]  = Bv * dist;
    o[10 * M_PER_B] = Cv * a1; o[11 * M_PER_B] = Cv * a2; o[12 * M_PER_B] = Cv * a3;
    g_wt[(size_t)b * M_PER_B + col] = (lane == 0) ? (float)(33 - c) : 1.f;
}

// ---------------- K3b: zero the pad tail (tot .. padded) ----------------
__global__ void __launch_bounds__(256) pad_kernel()
{
    const int b = blockIdx.x;
    const int tot = g_meta[b * 2 + 0];
    const int pad = g_meta[b * 2 + 1];
    for (int col = tot + threadIdx.x; col < pad; col += 256) {
        float* o = g_x0 + (size_t)b * 13 * M_PER_B + col;
#pragma unroll
        for (int r = 0; r < 13; r++) o[r * M_PER_B] = 0.f;
        g_wt[(size_t)b * M_PER_B + col] = 0.f;
    }
}

// 32 FFMA2 block: 8 outputs x 8 cols
#define FMA_CH(W0, W1, W2, W3, Y0, Y1)            \
    do {                                          \
        ffma2(acc[0][0], (W0).x, (Y0).x);         \
        ffma2(acc[0][1], (W0).x, (Y0).y);         \
        ffma2(acc[0][2], (W0).x, (Y1).x);         \
        ffma2(acc[0][3], (W0).x, (Y1).y);         \
        ffma2(acc[1][0], (W0).y, (Y0).x);         \
        ffma2(acc[1][1], (W0).y, (Y0).y);         \
        ffma2(acc[1][2], (W0).y, (Y1).x);         \
        ffma2(acc[1][3], (W0).y, (Y1).y);         \
        ffma2(acc[2][0], (W1).x, (Y0).x);         \
        ffma2(acc[2][1], (W1).x, (Y0).y);         \
        ffma2(acc[2][2], (W1).x, (Y1).x);         \
        ffma2(acc[2][3], (W1).x, (Y1).y);         \
        ffma2(acc[3][0], (W1).y, (Y0).x);         \
        ffma2(acc[3][1], (W1).y, (Y0).y);         \
        ffma2(acc[3][2], (W1).y, (Y1).x);         \
        ffma2(acc[3][3], (W1).y, (Y1).y);         \
        ffma2(acc[4][0], (W2).x, (Y0).x);         \
        ffma2(acc[4][1], (W2).x, (Y0).y);         \
        ffma2(acc[4][2], (W2).x, (Y1).x);         \
        ffma2(acc[4][3], (W2).x, (Y1).y);         \
        ffma2(acc[5][0], (W2).y, (Y0).x);         \
        ffma2(acc[5][1], (W2).y, (Y0).y);         \
        ffma2(acc[5][2], (W2).y, (Y1).x);         \
        ffma2(acc[5][3], (W2).y, (Y1).y);         \
        ffma2(acc[6][0], (W3).x, (Y0).x);         \
        ffma2(acc[6][1], (W3).x, (Y0).y);         \
        ffma2(acc[6][2], (W3).x, (Y1).x);         \
        ffma2(acc[6][3], (W3).x, (Y1).y);         \
        ffma2(acc[7][0], (W3).y, (Y0).x);         \
        ffma2(acc[7][1], (W3).y, (Y0).y);         \
        ffma2(acc[7][2], (W3).y, (Y1).x);         \
        ffma2(acc[7][3], (W3).y, (Y1).y);         \
    } while (0)

// ---------------- fused GEMM + (input GN/ReLU) + weighted stats -------------
// LAYER 0: 13->64 (x0->x1); LAYER 1: 64->64 GN0 (x1->x2); LAYER 2: 64->128 GN1 (x2->y2)
template <int LAYER>
__global__ void __launch_bounds__(LAYER == 2 ? 512 : 256, LAYER == 2 ? 1 : 2)
gemm_gn_kernel(const float* __restrict__ W, const float* __restrict__ gamma,
               const float* __restrict__ beta)
{
    constexpr int C     = (LAYER == 0) ? 13 : 64;
    constexpr int O     = (LAYER == 2) ? 128 : 64;
    constexpr int NT    = (LAYER == 2) ? 512 : 256;
    constexpr bool GN_IN = (LAYER > 0);

    const int tid = threadIdx.x;
    const int b   = blockIdx.y;
    const int m0  = blockIdx.x * 256;

    if (m0 >= g_meta[b * 2 + 1]) {   // beyond padded column count: no work
        if (tid < 8) {
            float* pp = g_part[LAYER]
                        + (((size_t)b * gridDim.x + blockIdx.x) * 8 + tid) * 2;
            pp[0] = 0.f;
            pp[1] = 0.f;
        }
        return;
    }

    extern __shared__ unsigned char smraw[];
    float2* Wp     = (float2*)smraw;                                 // [C][O] {w,w}
    float*  Xs     = (float*)(smraw + sizeof(float2) * O * C);       // [C][256]
    float*  sScale = Xs + C * 256;
    float*  sShift = sScale + 64;
    float*  sWsum  = sShift + 64;

    for (int idx = tid; idx < O * C; idx += NT) {
        int o = idx / C, c = idx - o * C;
        float w = W[idx];
        Wp[c * O + o] = make_float2(w, w);
    }
    if (GN_IN && tid < C) {
        const float* mr = g_mr[LAYER - 1] + b * 16;
        int gg = tid >> 3;
        float s = mr[gg * 2 + 1] * gamma[tid];
        sScale[tid] = s;
        sShift[tid] = beta[tid] - mr[gg * 2] * s;
    }
    __syncthreads();

    const float* xin = (LAYER == 0) ? g_x0 : ((LAYER == 1) ? g_x1 : g_x2);
    const float* xbp = xin + (size_t)b * C * M_PER_B + m0;
    for (int idx = tid; idx < C * 64; idx += NT) {
        int ci = idx >> 6;
        int c4 = (idx & 63) << 2;
        float4 v = *(const float4*)&xbp[(size_t)ci * M_PER_B + c4];
        if (GN_IN) {
            float s = sScale[ci], t = sShift[ci];
            v.x = fmaxf(s * v.x + t, 0.f);
            v.y = fmaxf(s * v.y + t, 0.f);
            v.z = fmaxf(s * v.z + t, 0.f);
            v.w = fmaxf(s * v.w + t, 0.f);
        }
        *(float4*)&Xs[ci * 256 + c4] = v;
    }
    __syncthreads();

    const int ob = tid >> 5;
    const int cg = tid & 31;
    const float* xcol = Xs + cg * 4;
    const unsigned long long* wb64 = (const unsigned long long*)Wp + ob * 8;

    unsigned long long acc[8][4];
#pragma unroll
    for (int a = 0; a < 8; a++) {
        acc[a][0] = 0ull; acc[a][1] = 0ull; acc[a][2] = 0ull; acc[a][3] = 0ull;
    }

#pragma unroll 4
    for (int i = 0; i < C; i++) {
        ulonglong2 y0 = *(const ulonglong2*)&xcol[i * 256];
        ulonglong2 y1 = *(const ulonglong2*)&xcol[i * 256 + 128];
        const ulonglong2* wr = (const ulonglong2*)(wb64 + (size_t)i * O);
        ulonglong2 w0 = wr[0], w1 = wr[1], w2 = wr[2], w3 = wr[3];
        FMA_CH(w0, w1, w2, w3, y0, y1);
    }

    // store raw outputs (compacted layout)
    float* xo = ((LAYER == 0) ? g_x1 : ((LAYER == 1) ? g_x2 : g_y2))
                + (size_t)b * O * M_PER_B + m0 + cg * 4;
#pragma unroll
    for (int oo = 0; oo < 8; oo++) {
        float4 v0, v1;
        v0.x = lo32(acc[oo][0]); v0.y = hi32(acc[oo][0]);
        v0.z = lo32(acc[oo][1]); v0.w = hi32(acc[oo][1]);
        v1.x = lo32(acc[oo][2]); v1.y = hi32(acc[oo][2]);
        v1.z = lo32(acc[oo][3]); v1.w = hi32(acc[oo][3]);
        *(float4*)&xo[(size_t)(ob * 8 + oo) * M_PER_B]       = v0;
        *(float4*)&xo[(size_t)(ob * 8 + oo) * M_PER_B + 128] = v1;
    }

    // ---- weighted GN stats: S = sum wt*y, Q = sum wt*y^2 ----
    {
        const float* wtp = g_wt + (size_t)b * M_PER_B + m0 + cg * 4;
        float4 wa4 = *(const float4*)wtp;
        float4 wb4 = *(const float4*)(wtp + 128);
        float wts[8] = {wa4.x, wa4.y, wa4.z, wa4.w, wb4.x, wb4.y, wb4.z, wb4.w};
        float colS[8] = {0, 0, 0, 0, 0, 0, 0, 0};
        float colQ[8] = {0, 0, 0, 0, 0, 0, 0, 0};
#pragma unroll
        for (int oo = 0; oo < 8; oo++) {
#pragma unroll
            for (int p = 0; p < 4; p++) {
                float v0 = lo32(acc[oo][p]), v1 = hi32(acc[oo][p]);
                colS[2 * p]     += v0;
                colQ[2 * p]     += v0 * v0;
                colS[2 * p + 1] += v1;
                colQ[2 * p + 1] += v1 * v1;
            }
        }
        float S = 0.f, Q = 0.f;
#pragma unroll
        for (int j = 0; j < 8; j++) {
            S += wts[j] * colS[j];
            Q += wts[j] * colQ[j];
        }
#pragma unroll
        for (int d = 16; d > 0; d >>= 1) {
            S += __shfl_xor_sync(0xffffffffu, S, d);
            Q += __shfl_xor_sync(0xffffffffu, Q, d);
        }
        if ((tid & 31) == 0) {
            sWsum[ob * 2 + 0] = S;
            sWsum[ob * 2 + 1] = Q;
        }
    }
    __syncthreads();
    if (tid < 8) {
        float S, Q;
        if (O == 64) {                       // group g == warp g
            S = sWsum[tid * 2 + 0];
            Q = sWsum[tid * 2 + 1];
        } else {                             // O=128: group g = warps {2g, 2g+1}
            S = sWsum[(2 * tid) * 2 + 0] + sWsum[(2 * tid + 1) * 2 + 0];
            Q = sWsum[(2 * tid) * 2 + 1] + sWsum[(2 * tid + 1) * 2 + 1];
        }
        float* pp = g_part[LAYER] + (((size_t)b * gridDim.x + blockIdx.x) * 8 + tid) * 2;
        pp[0] = S;
        pp[1] = Q;
    }
}

// ---------------- per-(b,group) stats reduce ----------------
template <int LAYER>
__global__ void __launch_bounds__(256) reduce_stats_kernel()
{
    constexpr float INV = (LAYER == 2) ? (1.f / 2097152.f) : (1.f / 1048576.f);
    const int b = blockIdx.x >> 3, g = blockIdx.x & 7;
    __shared__ float sS[256], sQ[256];
    float S = 0.f, Q = 0.f;
    for (int mb = threadIdx.x; mb < 512; mb += 256) {
        const float* p = g_part[LAYER] + (((size_t)b * 512 + mb) * 8 + g) * 2;
        S += p[0];
        Q += p[1];
    }
    sS[threadIdx.x] = S; sQ[threadIdx.x] = Q;
    __syncthreads();
    for (int d = 128; d > 0; d >>= 1) {
        if (threadIdx.x < d) {
            sS[threadIdx.x] += sS[threadIdx.x + d];
            sQ[threadIdx.x] += sQ[threadIdx.x + d];
        }
        __syncthreads();
    }
    if (threadIdx.x == 0) {
        float mean = sS[0] * INV;
        float var  = sQ[0] * INV - mean * mean;
        g_mr[LAYER][b * 16 + g * 2 + 0] = mean;
        g_mr[LAYER][b * 16 + g * 2 + 1] = rsqrtf(var + 1e-5f);
    }
}

// ---------------- segmented max/min over each point's k-range ----------------
__global__ void __launch_bounds__(128) segmax_kernel()
{
    const int warp = threadIdx.x >> 5;
    const int lane = threadIdx.x & 31;
    const int n = blockIdx.x * 4 + warp;
    const int b = blockIdx.y;

    const int c   = g_cnt[b * NPTS + n];
    const int off = g_off[b * NPTS + n];
    const float* y = g_y2 + (size_t)b * 128 * M_PER_B + off;
    const bool in = lane < c;

#pragma unroll 4
    for (int o = 0; o < 128; o++) {
        float v = in ? y[(size_t)o * M_PER_B + lane] : 0.f;
        float mx = in ? v : -FLT_MAX;
        float mn = in ? v : FLT_MAX;
#pragma unroll
        for (int d = 16; d > 0; d >>= 1) {
            mx = fmaxf(mx, __shfl_xor_sync(0xffffffffu, mx, d));
            mn = fminf(mn, __shfl_xor_sync(0xffffffffu, mn, d));
        }
        if (lane == 0) {
            size_t base = ((size_t)b * 128 + o) * NPTS + n;
            g_mx[base] = mx;
            g_mn[base] = mn;
        }
    }
}

// ---------------- finalize ----------------
__global__ void __launch_bounds__(256) finalize_kernel(
    const float* __restrict__ gamma, const float* __restrict__ beta,
    float* __restrict__ out)
{
    int i = blockIdx.x * 256 + threadIdx.x;       // [b][o][n], 2*128*4096
    int o = (i >> 12) & 127;
    int b = i >> 19;
    int g = o >> 4;
    const float* mr = g_mr[2] + b * 16 + g * 2;
    float s = mr[1] * gamma[o];
    float t = beta[o] - mr[0] * s;
    float v = (s >= 0.f) ? (s * g_mx[i] + t) : (s * g_mn[i] + t);
    out[i] = fmaxf(v, 0.f);
    out[2 * 128 * NPTS + i] = v;
}

// ---------------- launch ----------------
extern "C" void kernel_launch(void* const* d_in, const int* in_sizes, int n_in,
                              void* d_out, int out_size)
{
    const float* feature = (const float*)d_in[0];
    const float* xyz     = (const float*)d_in[1];
    const float* w0  = (const float*)d_in[2];
    const float* gg0 = (const float*)d_in[3];
    const float* gb0 = (const float*)d_in[4];
    const float* w1  = (const float*)d_in[5];
    const float* gg1 = (const float*)d_in[6];
    const float* gb1 = (const float*)d_in[7];
    const float* w2  = (const float*)d_in[8];
    const float* gg2 = (const float*)d_in[9];
    const float* gb2 = (const float*)d_in[10];
    const float* wa  = (const float*)d_in[11];
    const float* wb  = (const float*)d_in[12];
    const float* wc  = (const float*)d_in[13];
    float* out = (float*)d_out;

    const int sm0 = 64 * 13 * 8   + 13 * 256 * 4 + 512 + 8 * 8;
    const int sm1 = 64 * 64 * 8   + 64 * 256 * 4 + 512 + 8 * 8;
    const int sm2 = 128 * 64 * 8  + 64 * 256 * 4 + 512 + 16 * 8;
    cudaFuncSetAttribute(gemm_gn_kernel<0>, cudaFuncAttributeMaxDynamicSharedMemorySize, sm0);
    cudaFuncSetAttribute(gemm_gn_kernel<1>, cudaFuncAttributeMaxDynamicSharedMemorySize, sm1);
    cudaFuncSetAttribute(gemm_gn_kernel<2>, cudaFuncAttributeMaxDynamicSharedMemorySize, sm2);

    ball_count_kernel<<<dim3(512, 2), 256>>>(xyz);
    scan_kernel<<<2, 1024>>>();
    feat_kernel<<<dim3(512, 2), 256>>>(xyz, feature, wa, wb, wc);
    pad_kernel<<<2, 256>>>();

    gemm_gn_kernel<0><<<dim3(512, 2), 256, sm0>>>(w0, gg0, gb0);
    reduce_stats_kernel<0><<<16, 256>>>();

    gemm_gn_kernel<1><<<dim3(512, 2), 256, sm1>>>(w1, gg0, gb0);
    reduce_stats_kernel<1><<<16, 256>>>();

    gemm_gn_kernel<2><<<dim3(512, 2), 512, sm2>>>(w2, gg1, gb1);
    reduce_stats_kernel<2><<<16, 256>>>();

    segmax_kernel<<<dim3(1024, 2), 128>>>();
    finalize_kernel<<<4096, 256>>>(gg2, gb2, out);
}